// round 14
// baseline (speedup 1.0000x reference)
#include <cuda_runtime.h>
#include <cuda_fp16.h>
#include <math.h>
#include <stdint.h>

#define NP 16384
#define NR 8192
#define GRIDN 13
#define NCELL (GRIDN*GRIDN*GRIDN)
#define CAP 64
#define RADIUS2 (0.075f*0.075f)

// ---------------- static scratch ----------------
__device__ int    d_cellCnt[NCELL];
__device__ float4 d_cellPts[NCELL*CAP];
__device__ int    d_nbr[NP*3];
__device__ unsigned short d_rgbt[NR*128];   // rgb features point-major fp16
__device__ unsigned short d_hA[384*NP];
__device__ unsigned short d_hB[384*NP];
__device__ unsigned short d_hC[256*NP];
__device__ unsigned short d_hw[382976];     // weights fp16 k-major
__device__ float  d_bns[5*384];
__device__ float  d_bnt[5*384];

// ---------------- PTX helpers ----------------
__device__ __forceinline__ uint32_t smem_u32(const void* p) {
    uint32_t a;
    asm("{ .reg .u64 t; cvta.to.shared.u64 t, %1; cvt.u32.u64 %0, t; }" : "=r"(a) : "l"(p));
    return a;
}
__device__ __forceinline__ void cpasync16s(uint32_t s, const void* g, int sz) {
    asm volatile("cp.async.cg.shared.global [%0], [%1], 16, %2;" :: "r"(s), "l"(g), "r"(sz));
}
#define CP_COMMIT() asm volatile("cp.async.commit_group;")
#define LDSM4(r0,r1,r2,r3,a) \
    asm volatile("ldmatrix.sync.aligned.m8n8.x4.shared.b16 {%0,%1,%2,%3},[%4];" \
        : "=r"(r0),"=r"(r1),"=r"(r2),"=r"(r3) : "r"(a))
#define LDSM4T(r0,r1,r2,r3,a) \
    asm volatile("ldmatrix.sync.aligned.m8n8.x4.trans.shared.b16 {%0,%1,%2,%3},[%4];" \
        : "=r"(r0),"=r"(r1),"=r"(r2),"=r"(r3) : "r"(a))
__device__ __forceinline__ void mma16(float* c, const uint32_t* a, uint32_t b0, uint32_t b1) {
    asm volatile(
        "mma.sync.aligned.m16n8k16.row.col.f32.f16.f16.f32 "
        "{%0,%1,%2,%3},{%4,%5,%6,%7},{%8,%9},{%0,%1,%2,%3};"
        : "+f"(c[0]), "+f"(c[1]), "+f"(c[2]), "+f"(c[3])
        : "r"(a[0]), "r"(a[1]), "r"(a[2]), "r"(a[3]), "r"(b0), "r"(b1));
}

// ---------------- spatial grid + 3NN ----------------
__global__ void k_clear() {
    int i = blockIdx.x*blockDim.x + threadIdx.x;
    if (i < NCELL) d_cellCnt[i] = 0;
}
__device__ __forceinline__ int cidx(float v) {
    int c = (int)(v * (float)GRIDN);
    return c < 0 ? 0 : (c > GRIDN-1 ? GRIDN-1 : c);
}
__global__ void k_build(const float* __restrict__ rgb) {
    int i = blockIdx.x*blockDim.x + threadIdx.x;
    if (i >= NR) return;
    float x = rgb[3*i], y = rgb[3*i+1], z = rgb[3*i+2];
    int c = (cidx(x)*GRIDN + cidx(y))*GRIDN + cidx(z);
    int p = atomicAdd(&d_cellCnt[c], 1);
    if (p < CAP) d_cellPts[c*CAP + p] = make_float4(x, y, z, __int_as_float(i));
}
__global__ void k_3nn(const float* __restrict__ pcd) {
    int i = blockIdx.x*blockDim.x + threadIdx.x;
    if (i >= NP) return;
    float x = pcd[3*i], y = pcd[3*i+1], z = pcd[3*i+2];
    int cx = cidx(x), cy = cidx(y), cz = cidx(z);
    int x0 = max(cx-1,0), x1 = min(cx+1,GRIDN-1);
    int y0 = max(cy-1,0), y1 = min(cy+1,GRIDN-1);
    int z0 = max(cz-1,0), z1 = min(cz+1,GRIDN-1);
    float b0 = 3.4e38f, b1 = 3.4e38f, b2 = 3.4e38f;
    int   i0 = NR, i1 = NR, i2 = NR;
    for (int ax = x0; ax <= x1; ax++)
    for (int ay = y0; ay <= y1; ay++)
    for (int az = z0; az <= z1; az++) {
        int c = (ax*GRIDN + ay)*GRIDN + az;
        int cnt = min(d_cellCnt[c], CAP);
        const float4* pts = &d_cellPts[c*CAP];
        for (int p = 0; p < cnt; p++) {
            float4 q = pts[p];
            float dx = x - q.x, dy = y - q.y, dz = z - q.z;
            float d = fmaf(dx, dx, fmaf(dy, dy, dz*dz));
            if (d <= RADIUS2 && d < b2) {
                int qi = __float_as_int(q.w);
                if (d < b0)      { b2=b1;i2=i1; b1=b0;i1=i0; b0=d;i0=qi; }
                else if (d < b1) { b2=b1;i2=i1; b1=d; i1=qi; }
                else             { b2=d; i2=qi; }
            }
        }
    }
    d_nbr[3*i] = i0; d_nbr[3*i+1] = i1; d_nbr[3*i+2] = i2;
}

// ---------------- ch-major fp32 -> point-major fp16 transpose ----------------
__global__ void k_trans16(const float* __restrict__ in, unsigned short* __restrict__ out,
                          int C, int N, int ostride, int ocoff) {
    __shared__ float t[32][33];
    int nb = blockIdx.x * 32;
    int cb = blockIdx.y * 32;
    int tx = threadIdx.x, ty = threadIdx.y;
    #pragma unroll
    for (int i = 0; i < 32; i += 8) {
        int c = cb + ty + i;
        t[ty+i][tx] = (c < C) ? in[(size_t)c*N + nb + tx] : 0.f;
    }
    __syncthreads();
    #pragma unroll
    for (int i = 0; i < 32; i += 8) {
        int c = cb + tx;
        if (c < C) out[(size_t)(nb + ty + i)*ostride + ocoff + c] =
            __half_as_ushort(__float2half(t[tx][ty+i]));
    }
}

// ---------------- gather (fp16): x_cat -> hA, maxf -> hC cols 128..255 ----------------
__global__ void k_gather16(const unsigned short* __restrict__ rgbt) {
    int t = blockIdx.x*blockDim.x + threadIdx.x;
    int n = t >> 5, lane = t & 31;
    if (n >= NP) return;
    int n0 = d_nbr[3*n], n1 = d_nbr[3*n+1], n2 = d_nbr[3*n+2];
    uint2 z = make_uint2(0u, 0u);
    uint2 u0 = (n0 < NR) ? *(const uint2*)&rgbt[(size_t)n0*128 + lane*4] : z;
    uint2 u1 = (n1 < NR) ? *(const uint2*)&rgbt[(size_t)n1*128 + lane*4] : z;
    uint2 u2 = (n2 < NR) ? *(const uint2*)&rgbt[(size_t)n2*128 + lane*4] : z;
    size_t rb = (size_t)n*384 + lane*4;
    *(uint2*)&d_hA[rb]       = u0;
    *(uint2*)&d_hA[rb + 128] = u1;
    *(uint2*)&d_hA[rb + 256] = u2;
    __half2 a0 = *(__half2*)&u0.x, a1 = *(__half2*)&u0.y;
    __half2 b0 = *(__half2*)&u1.x, b1 = *(__half2*)&u1.y;
    __half2 c0 = *(__half2*)&u2.x, c1 = *(__half2*)&u2.y;
    __half2 m0 = __hmax2(__hmax2(a0, b0), c0);
    __half2 m1 = __hmax2(__hmax2(a1, b1), c1);
    uint2 mu; mu.x = *(uint32_t*)&m0; mu.y = *(uint32_t*)&m1;
    *(uint2*)&d_hC[(size_t)n*256 + 128 + lane*4] = mu;
}

// ---------------- fold BN ----------------
__global__ void k_bnprep5(const float* b0, const float* b1, const float* b2,
                          const float* b3, const float* b4) {
    const int Cs[5] = {384, 256, 160, 160, 128};
    const float* ps[5] = {b0, b1, b2, b3, b4};
    int slot = blockIdx.x;
    const float* bn = ps[slot];
    int C = Cs[slot];
    for (int c = threadIdx.x; c < C; c += blockDim.x) {
        float g = bn[c], b = bn[C+c], m = bn[2*C+c], v = bn[3*C+c];
        float s = g * rsqrtf(v + 1e-5f);
        d_bns[slot*384 + c] = s;
        d_bnt[slot*384 + c] = b - m*s;
    }
}

// ---------------- weight convert fp32[M][K] -> fp16[K][M] ----------------
struct WSegs { const float* s[8]; int M[8]; int K[8]; int off[8]; };
__global__ void k_wcvt(WSegs ws) {
    int t = blockIdx.x*blockDim.x + threadIdx.x;
    #pragma unroll
    for (int i = 0; i < 8; i++) {
        int sz = ws.M[i] * ws.K[i];
        if (t < sz) {
            int m = t / ws.K[i], k = t % ws.K[i];
            d_hw[ws.off[i] + (size_t)k * ws.M[i] + m] = __half_as_ushort(__float2half(ws.s[i][t]));
            return;
        }
        t -= sz;
    }
}

// ---------------- fp16 tensor-core GEMM, templated BM (MT*64 pts), 3-stage cp.async ----------------
#define ASTR 72
#define BSTR 136
#define NSTG 3
template<int MT>
__global__ void __launch_bounds__(256, 2)
k_mma(const __half* __restrict__ X, const __half* __restrict__ W16,
      __half* __restrict__ Y, const float* __restrict__ bias,
      const float* __restrict__ bns, const float* __restrict__ bnt,
      int K, int Mout, int Cout, int coloff, int bnrelu)
{
    extern __shared__ __align__(16) unsigned char smem[];
    const int ABYTES = MT*64*ASTR*2;
    const int STAGE  = ABYTES + 64*BSTR*2;
    uint32_t sbase = smem_u32(smem);
    const int tid = threadIdx.x;
    const int wid = tid >> 5, lane = tid & 31;
    const int warp_m = wid & 3, warp_n = wid >> 2;
    const int by = blockIdx.y;
    const size_t rowbase = (size_t)blockIdx.x * (MT*64);
    const int NC = (K + 63) >> 6;
    const int li = lane & 15, h8 = (lane >> 4) << 3;

    float acc[MT][8][4];
    #pragma unroll
    for (int i = 0; i < MT; i++)
        #pragma unroll
        for (int j = 0; j < 8; j++)
            #pragma unroll
            for (int q = 0; q < 4; q++) acc[i][j][q] = 0.f;

    auto issue = [&](int c) {
        int s = c % NSTG;
        int k0 = c << 6;
        uint32_t As = sbase + s*STAGE;
        uint32_t Bs = As + ABYTES;
        #pragma unroll
        for (int i = 0; i < 2*MT; i++) {
            int idx = tid + i*256;
            int r = idx >> 3, q = idx & 7;
            int kg = k0 + q*8;
            int sz = (kg < K) ? 16 : 0;
            cpasync16s(As + (r*ASTR + q*8)*2,
                       X + (rowbase + r)*(size_t)K + min(kg, K-8), sz);
        }
        #pragma unroll
        for (int i = 0; i < 4; i++) {
            int idx = tid + i*256;
            int kr = idx >> 4, qn = idx & 15;
            int kg = k0 + kr;
            int ng = by*128 + qn*8;
            int sz = (kg < K && ng < Mout) ? 16 : 0;
            cpasync16s(Bs + (kr*BSTR + qn*8)*2,
                       W16 + (size_t)min(kg, K-1)*Mout + min(ng, Mout-8), sz);
        }
        CP_COMMIT();
    };

    issue(0);
    if (NC > 1) issue(1);

    for (int c = 0; c < NC; c++) {
        if (c + 2 < NC) issue(c + 2);
        int pending = min(2, NC - c - 1);
        if (pending >= 2)      asm volatile("cp.async.wait_group 2;");
        else if (pending == 1) asm volatile("cp.async.wait_group 1;");
        else                   asm volatile("cp.async.wait_group 0;");
        __syncthreads();
        uint32_t As = sbase + (c % NSTG)*STAGE;
        uint32_t Bs = As + ABYTES;
        #pragma unroll
        for (int kk = 0; kk < 64; kk += 16) {
            uint32_t a[MT][4];
            #pragma unroll
            for (int mt = 0; mt < MT; mt++) {
                uint32_t ad = As + (((warp_m*MT*16 + mt*16 + li)*ASTR) + kk + h8)*2;
                LDSM4(a[mt][0], a[mt][1], a[mt][2], a[mt][3], ad);
            }
            uint32_t b[4][4];
            #pragma unroll
            for (int nt2 = 0; nt2 < 4; nt2++) {
                uint32_t bd = Bs + ((kk + li)*BSTR + warp_n*64 + nt2*16 + h8)*2;
                LDSM4T(b[nt2][0], b[nt2][1], b[nt2][2], b[nt2][3], bd);
            }
            #pragma unroll
            for (int mt = 0; mt < MT; mt++)
                #pragma unroll
                for (int nt = 0; nt < 8; nt++)
                    mma16(acc[mt][nt], a[mt], b[nt>>1][(nt&1)*2], b[nt>>1][(nt&1)*2+1]);
        }
        __syncthreads();
    }

    // epilogue: bias/BN/ReLU -> fp16
    const int g = lane >> 2, tp = (lane & 3) * 2;
    #pragma unroll
    for (int nt = 0; nt < 8; nt++) {
        int base = by*128 + warp_n*64 + nt*8;
        if (base >= Mout) break;
        int m = base + tp;
        float bi0 = __ldg(&bias[m]), bi1 = __ldg(&bias[m+1]);
        float s0 = 0.f, s1 = 0.f, t0 = 0.f, t1 = 0.f;
        if (bnrelu) {
            s0 = __ldg(&bns[m]); s1 = __ldg(&bns[m+1]);
            t0 = __ldg(&bnt[m]); t1 = __ldg(&bnt[m+1]);
        }
        #pragma unroll
        for (int mt = 0; mt < MT; mt++) {
            #pragma unroll
            for (int h = 0; h < 2; h++) {
                int pt = (int)rowbase + warp_m*MT*16 + mt*16 + h*8 + g;
                float x0 = acc[mt][nt][2*h]   + bi0;
                float x1 = acc[mt][nt][2*h+1] + bi1;
                if (bnrelu) {
                    x0 = fmaxf(fmaf(x0, s0, t0), 0.f);
                    x1 = fmaxf(fmaf(x1, s1, t1), 0.f);
                }
                *(__half2*)&Y[(size_t)pt*Cout + coloff + m] = __floats2half2_rn(x0, x1);
            }
        }
    }
}

// ---------------- fused heads: score + L2-normalized vf ----------------
__global__ void k_heads(const float* __restrict__ w, const float* __restrict__ b,
                        const unsigned short* __restrict__ S,
                        const unsigned short* __restrict__ FP,
                        float* __restrict__ outScore, float* __restrict__ outVf) {
    int t = blockIdx.x*blockDim.x + threadIdx.x;
    int n = t >> 5, lane = t & 31;
    if (n >= NP) return;
    uint2 su = *(const uint2*)&S[(size_t)n*128 + lane*4];
    __half2 s0 = *(__half2*)&su.x, s1 = *(__half2*)&su.y;
    float4 wv = *(const float4*)&w[lane*4];
    float sacc = __low2float(s0)*wv.x + __high2float(s0)*wv.y
               + __low2float(s1)*wv.z + __high2float(s1)*wv.w;
    uint2 fu = *(const uint2*)&FP[(size_t)n*128 + lane*4];
    __half2 f0 = *(__half2*)&fu.x, f1 = *(__half2*)&fu.y;
    float v0 = __low2float(f0), v1 = __high2float(f0);
    float v2 = __low2float(f1), v3 = __high2float(f1);
    float ss = v0*v0 + v1*v1 + v2*v2 + v3*v3;
    #pragma unroll
    for (int o = 16; o > 0; o >>= 1) {
        sacc += __shfl_xor_sync(0xffffffff, sacc, o);
        ss   += __shfl_xor_sync(0xffffffff, ss, o);
    }
    if (lane == 0) outScore[n] = 1.f / (1.f + expf(-(sacc + b[0])));
    float inv = 1.f / fmaxf(sqrtf(ss), 1e-12f);
    *(float4*)&outVf[(size_t)n*128 + lane*4] =
        make_float4(v0*inv, v1*inv, v2*inv, v3*inv);
}

extern "C" void kernel_launch(void* const* d_in, const int* in_sizes, int n_in,
                              void* d_out, int out_size) {
    const float* pcd_xyz = (const float*)d_in[0];
    const float* rgb_xyz = (const float*)d_in[1];
    const float* pcd_f   = (const float*)d_in[2];
    const float* rgb_f   = (const float*)d_in[3];
    const float* cc1_w = (const float*)d_in[4];  const float* cc1_b = (const float*)d_in[5];
    const float* cc_bn = (const float*)d_in[6];
    const float* cc2_w = (const float*)d_in[7];  const float* cc2_b = (const float*)d_in[8];
    const float* co1_w = (const float*)d_in[9];  const float* co1_b = (const float*)d_in[10];
    const float* co_bn = (const float*)d_in[11];
    const float* co2_w = (const float*)d_in[12]; const float* co2_b = (const float*)d_in[13];
    const float* dh1_w = (const float*)d_in[14]; const float* dh1_b = (const float*)d_in[15];
    const float* dh1_bn= (const float*)d_in[16];
    const float* dh2_w = (const float*)d_in[17]; const float* dh2_b = (const float*)d_in[18];
    const float* dh2_bn= (const float*)d_in[19];
    const float* dh3_w = (const float*)d_in[20]; const float* dh3_b = (const float*)d_in[21];
    const float* sh1_w = (const float*)d_in[22]; const float* sh1_b = (const float*)d_in[23];
    const float* sh_bn = (const float*)d_in[24];
    const float* sh2_w = (const float*)d_in[25]; const float* sh2_b = (const float*)d_in[26];
    float* out = (float*)d_out;

    unsigned short *hw, *rgbt, *hA, *hB, *hC;
    float *bns, *bnt;
    cudaGetSymbolAddress((void**)&hw, d_hw);
    cudaGetSymbolAddress((void**)&rgbt, d_rgbt);
    cudaGetSymbolAddress((void**)&hA, d_hA);
    cudaGetSymbolAddress((void**)&hB, d_hB);
    cudaGetSymbolAddress((void**)&hC, d_hC);
    cudaGetSymbolAddress((void**)&bns, d_bns);
    cudaGetSymbolAddress((void**)&bnt, d_bnt);

    const int STAGE1 = 64*ASTR*2 + 64*BSTR*2;    // 26624
    const int STAGE2 = 128*ASTR*2 + 64*BSTR*2;   // 35840
    cudaFuncSetAttribute(k_mma<1>, cudaFuncAttributeMaxDynamicSharedMemorySize, NSTG*STAGE1);
    cudaFuncSetAttribute(k_mma<2>, cudaFuncAttributeMaxDynamicSharedMemorySize, NSTG*STAGE2);

    // weight segment table: fp32 [M][K] -> fp16 [K][M]
    WSegs ws;
    const float* srcs[8] = {cc1_w, cc2_w, co1_w, co2_w, dh1_w, dh2_w, dh3_w, sh1_w};
    int Ms[8]   = {384, 128, 256, 128, 160, 160, 128, 128};
    int Ks[8]   = {384, 384, 256, 256, 160, 160, 160, 128};
    int offs[8] = {0, 147456, 196608, 262144, 294912, 320512, 346112, 366592};
    for (int i = 0; i < 8; i++) { ws.s[i] = srcs[i]; ws.M[i] = Ms[i]; ws.K[i] = Ks[i]; ws.off[i] = offs[i]; }

    // ---- prep ----
    k_clear<<<(NCELL+255)/256, 256>>>();
    k_build<<<(NR+255)/256, 256>>>(rgb_xyz);
    k_3nn<<<(NP+127)/128, 128>>>(pcd_xyz);
    k_trans16<<<dim3(NR/32, 4), dim3(32,8)>>>(rgb_f, rgbt, 128, NR, 128, 0);
    k_gather16<<<(NP*32)/256, 256>>>(rgbt);
    k_bnprep5<<<5, 384>>>(cc_bn, co_bn, dh1_bn, dh2_bn, sh_bn);
    k_wcvt<<<(382976+255)/256, 256>>>(ws);
    cudaMemcpyAsync(out, pcd_xyz, (size_t)NP*3*sizeof(float), cudaMemcpyDeviceToDevice);

    // ---- fp16 mma GEMM chain ----
    const __half *XA = (const __half*)hA, *XB = (const __half*)hB, *XC = (const __half*)hC;
    __half *YA = (__half*)hA, *YB = (__half*)hB, *YC = (__half*)hC;
    const __half* W = (const __half*)hw;
    // cc1: hA[384] -> hB[384], BN+ReLU   (BM=64: 256x3 = 768 CTAs)
    k_mma<1><<<dim3(256,3), 256, NSTG*STAGE1>>>(XA, W+offs[0], YB, cc1_b, bns,       bnt,       384, 384, 384, 0, 1);
    // cc2: hB[384] -> hC cols 0..127 (stride 256)
    k_mma<1><<<dim3(256,1), 256, NSTG*STAGE1>>>(XB, W+offs[1], YC, cc2_b, nullptr,   nullptr,   384, 128, 256, 0, 0);
    // co1: hC[256] -> hA[256], BN+ReLU   (BM=128: 128x2)
    k_mma<2><<<dim3(128,2), 256, NSTG*STAGE2>>>(XC, W+offs[2], YA, co1_b, bns+384,   bnt+384,   256, 256, 256, 0, 1);
    // pcd_features -> hB cols 0..31 (stride 160)
    k_trans16<<<dim3(NP/32, 1), dim3(32,8)>>>(pcd_f, hB, 32, NP, 160, 0);
    // co2: hA[256] -> hB cols 32..159
    k_mma<1><<<dim3(256,1), 256, NSTG*STAGE1>>>(XA, W+offs[3], YB, co2_b, nullptr,   nullptr,   256, 128, 160, 32, 0);
    // dh1: hB[160] -> hC[160], BN+ReLU
    k_mma<2><<<dim3(128,2), 256, NSTG*STAGE2>>>(XB, W+offs[4], YC, dh1_b, bns+2*384, bnt+2*384, 160, 160, 160, 0, 1);
    // dh2: hC[160] -> hA[160], BN+ReLU
    k_mma<2><<<dim3(128,2), 256, NSTG*STAGE2>>>(XC, W+offs[5], YA, dh2_b, bns+3*384, bnt+3*384, 160, 160, 160, 0, 1);
    // dh3: hA[160] -> hB[128]  (fp)
    k_mma<1><<<dim3(256,1), 256, NSTG*STAGE1>>>(XA, W+offs[6], YB, dh3_b, nullptr,   nullptr,   160, 128, 128, 0, 0);
    // sh1: hB[128] -> hC[128], BN+ReLU
    k_mma<1><<<dim3(256,1), 256, NSTG*STAGE1>>>(XB, W+offs[7], YC, sh1_b, bns+4*384, bnt+4*384, 128, 128, 128, 0, 1);

    // ---- outputs: [pcd_xyz NP*3][scores NP][vf NP*128] ----
    k_heads<<<(NP*32)/256, 256>>>(sh2_w, sh2_b, hC, hB,
                                  out + (size_t)NP*3, out + (size_t)NP*4);
}

// round 15
// speedup vs baseline: 1.0399x; 1.0399x over previous
#include <cuda_runtime.h>
#include <cuda_fp16.h>
#include <math.h>
#include <stdint.h>

#define NP 16384
#define NR 8192
#define GRIDN 13
#define NCELL (GRIDN*GRIDN*GRIDN)
#define CAP 64
#define RADIUS2 (0.075f*0.075f)

// ---------------- static scratch ----------------
__device__ int    d_cellCnt[NCELL];
__device__ float4 d_cellPts[NCELL*CAP];
__device__ int    d_nbr[NP*3];
__device__ unsigned short d_rgbt[NR*128];   // rgb features point-major fp16
__device__ unsigned short d_hA[384*NP];
__device__ unsigned short d_hB[384*NP];
__device__ unsigned short d_hC[256*NP];
__device__ unsigned short d_hw[382976];     // weights fp16 k-major
__device__ float  d_bns[5*384];
__device__ float  d_bnt[5*384];

// ---------------- PTX helpers ----------------
__device__ __forceinline__ uint32_t smem_u32(const void* p) {
    uint32_t a;
    asm("{ .reg .u64 t; cvta.to.shared.u64 t, %1; cvt.u32.u64 %0, t; }" : "=r"(a) : "l"(p));
    return a;
}
__device__ __forceinline__ void cpasync16s(uint32_t s, const void* g, int sz) {
    asm volatile("cp.async.cg.shared.global [%0], [%1], 16, %2;" :: "r"(s), "l"(g), "r"(sz));
}
#define CP_COMMIT() asm volatile("cp.async.commit_group;")
#define LDSM4(r0,r1,r2,r3,a) \
    asm volatile("ldmatrix.sync.aligned.m8n8.x4.shared.b16 {%0,%1,%2,%3},[%4];" \
        : "=r"(r0),"=r"(r1),"=r"(r2),"=r"(r3) : "r"(a))
#define LDSM4T(r0,r1,r2,r3,a) \
    asm volatile("ldmatrix.sync.aligned.m8n8.x4.trans.shared.b16 {%0,%1,%2,%3},[%4];" \
        : "=r"(r0),"=r"(r1),"=r"(r2),"=r"(r3) : "r"(a))
__device__ __forceinline__ void mma16(float* c, const uint32_t* a, uint32_t b0, uint32_t b1) {
    asm volatile(
        "mma.sync.aligned.m16n8k16.row.col.f32.f16.f16.f32 "
        "{%0,%1,%2,%3},{%4,%5,%6,%7},{%8,%9},{%0,%1,%2,%3};"
        : "+f"(c[0]), "+f"(c[1]), "+f"(c[2]), "+f"(c[3])
        : "r"(a[0]), "r"(a[1]), "r"(a[2]), "r"(a[3]), "r"(b0), "r"(b1));
}

// ---------------- spatial grid + 3NN ----------------
__device__ __forceinline__ int cidx(float v) {
    int c = (int)(v * (float)GRIDN);
    return c < 0 ? 0 : (c > GRIDN-1 ? GRIDN-1 : c);
}
__global__ void k_build(const float* __restrict__ rgb) {
    int i = blockIdx.x*blockDim.x + threadIdx.x;
    if (i >= NR) return;
    float x = rgb[3*i], y = rgb[3*i+1], z = rgb[3*i+2];
    int c = (cidx(x)*GRIDN + cidx(y))*GRIDN + cidx(z);
    int p = atomicAdd(&d_cellCnt[c], 1);
    if (p < CAP) d_cellPts[c*CAP + p] = make_float4(x, y, z, __int_as_float(i));
}
__global__ void k_3nn(const float* __restrict__ pcd) {
    int i = blockIdx.x*blockDim.x + threadIdx.x;
    if (i >= NP) return;
    float x = pcd[3*i], y = pcd[3*i+1], z = pcd[3*i+2];
    int cx = cidx(x), cy = cidx(y), cz = cidx(z);
    int x0 = max(cx-1,0), x1 = min(cx+1,GRIDN-1);
    int y0 = max(cy-1,0), y1 = min(cy+1,GRIDN-1);
    int z0 = max(cz-1,0), z1 = min(cz+1,GRIDN-1);
    float b0 = 3.4e38f, b1 = 3.4e38f, b2 = 3.4e38f;
    int   i0 = NR, i1 = NR, i2 = NR;
    for (int ax = x0; ax <= x1; ax++)
    for (int ay = y0; ay <= y1; ay++)
    for (int az = z0; az <= z1; az++) {
        int c = (ax*GRIDN + ay)*GRIDN + az;
        int cnt = min(d_cellCnt[c], CAP);
        const float4* pts = &d_cellPts[c*CAP];
        for (int p = 0; p < cnt; p++) {
            float4 q = pts[p];
            float dx = x - q.x, dy = y - q.y, dz = z - q.z;
            float d = fmaf(dx, dx, fmaf(dy, dy, dz*dz));
            if (d <= RADIUS2 && d < b2) {
                int qi = __float_as_int(q.w);
                if (d < b0)      { b2=b1;i2=i1; b1=b0;i1=i0; b0=d;i0=qi; }
                else if (d < b1) { b2=b1;i2=i1; b1=d; i1=qi; }
                else             { b2=d; i2=qi; }
            }
        }
    }
    d_nbr[3*i] = i0; d_nbr[3*i+1] = i1; d_nbr[3*i+2] = i2;
}

// ---------------- ch-major fp32 -> point-major fp16 transpose ----------------
__global__ void k_trans16(const float* __restrict__ in, unsigned short* __restrict__ out,
                          int C, int N, int ostride, int ocoff) {
    __shared__ float t[32][33];
    int nb = blockIdx.x * 32;
    int cb = blockIdx.y * 32;
    int tx = threadIdx.x, ty = threadIdx.y;
    #pragma unroll
    for (int i = 0; i < 32; i += 8) {
        int c = cb + ty + i;
        t[ty+i][tx] = (c < C) ? in[(size_t)c*N + nb + tx] : 0.f;
    }
    __syncthreads();
    #pragma unroll
    for (int i = 0; i < 32; i += 8) {
        int c = cb + tx;
        if (c < C) out[(size_t)(nb + ty + i)*ostride + ocoff + c] =
            __half_as_ushort(__float2half(t[tx][ty+i]));
    }
}

// ---------------- gather (fp16): x_cat -> hA, maxf -> hC cols 128..255 ----------------
__global__ void k_gather16(const unsigned short* __restrict__ rgbt) {
    int t = blockIdx.x*blockDim.x + threadIdx.x;
    int n = t >> 5, lane = t & 31;
    if (n >= NP) return;
    int n0 = d_nbr[3*n], n1 = d_nbr[3*n+1], n2 = d_nbr[3*n+2];
    uint2 z = make_uint2(0u, 0u);
    uint2 u0 = (n0 < NR) ? *(const uint2*)&rgbt[(size_t)n0*128 + lane*4] : z;
    uint2 u1 = (n1 < NR) ? *(const uint2*)&rgbt[(size_t)n1*128 + lane*4] : z;
    uint2 u2 = (n2 < NR) ? *(const uint2*)&rgbt[(size_t)n2*128 + lane*4] : z;
    size_t rb = (size_t)n*384 + lane*4;
    *(uint2*)&d_hA[rb]       = u0;
    *(uint2*)&d_hA[rb + 128] = u1;
    *(uint2*)&d_hA[rb + 256] = u2;
    __half2 a0 = *(__half2*)&u0.x, a1 = *(__half2*)&u0.y;
    __half2 b0 = *(__half2*)&u1.x, b1 = *(__half2*)&u1.y;
    __half2 c0 = *(__half2*)&u2.x, c1 = *(__half2*)&u2.y;
    __half2 m0 = __hmax2(__hmax2(a0, b0), c0);
    __half2 m1 = __hmax2(__hmax2(a1, b1), c1);
    uint2 mu; mu.x = *(uint32_t*)&m0; mu.y = *(uint32_t*)&m1;
    *(uint2*)&d_hC[(size_t)n*256 + 128 + lane*4] = mu;
}

// -------- fused prep: cell clear + BN fold + weight convert, one launch --------
struct WSegs { const float* s[8]; int M[8]; int K[8]; int off[8]; };
struct BNSrc { const float* p[5]; };
#define WCVT_TOT 382976
#define PREP_TOT (WCVT_TOT + NCELL + 1088)
__global__ void k_prep(WSegs ws, BNSrc bn) {
    int t = blockIdx.x*blockDim.x + threadIdx.x;
    if (t < WCVT_TOT) {
        #pragma unroll
        for (int i = 0; i < 8; i++) {
            int sz = ws.M[i] * ws.K[i];
            if (t < sz) {
                int m = t / ws.K[i], k = t % ws.K[i];
                d_hw[ws.off[i] + (size_t)k * ws.M[i] + m] =
                    __half_as_ushort(__float2half(ws.s[i][t]));
                return;
            }
            t -= sz;
        }
        return;
    }
    t -= WCVT_TOT;
    if (t < NCELL) { d_cellCnt[t] = 0; return; }
    t -= NCELL;
    // BN fold: slots concatenated {384,256,160,160,128}
    const int Cs[5] = {384, 256, 160, 160, 128};
    #pragma unroll
    for (int s = 0; s < 5; s++) {
        if (t < Cs[s]) {
            int C = Cs[s];
            const float* b = bn.p[s];
            float g = b[t], bb = b[C+t], m = b[2*C+t], v = b[3*C+t];
            float sc = g * rsqrtf(v + 1e-5f);
            d_bns[s*384 + t] = sc;
            d_bnt[s*384 + t] = bb - m*sc;
            return;
        }
        t -= Cs[s];
    }
}

// ---------------- fp16 tensor-core GEMM, templated BM (MT*64 pts), 3-stage cp.async ----------------
#define ASTR 72
#define BSTR 136
#define NSTG 3
template<int MT>
__global__ void __launch_bounds__(256, 2)
k_mma(const __half* __restrict__ X, const __half* __restrict__ W16,
      __half* __restrict__ Y, const float* __restrict__ bias,
      const float* __restrict__ bns, const float* __restrict__ bnt,
      int K, int Mout, int Cout, int coloff, int bnrelu)
{
    extern __shared__ __align__(16) unsigned char smem[];
    const int ABYTES = MT*64*ASTR*2;
    const int STAGE  = ABYTES + 64*BSTR*2;
    uint32_t sbase = smem_u32(smem);
    const int tid = threadIdx.x;
    const int wid = tid >> 5, lane = tid & 31;
    const int warp_m = wid & 3, warp_n = wid >> 2;
    const int by = blockIdx.y;
    const size_t rowbase = (size_t)blockIdx.x * (MT*64);
    const int NC = (K + 63) >> 6;
    const int li = lane & 15, h8 = (lane >> 4) << 3;

    float acc[MT][8][4];
    #pragma unroll
    for (int i = 0; i < MT; i++)
        #pragma unroll
        for (int j = 0; j < 8; j++)
            #pragma unroll
            for (int q = 0; q < 4; q++) acc[i][j][q] = 0.f;

    auto issue = [&](int c) {
        int s = c % NSTG;
        int k0 = c << 6;
        uint32_t As = sbase + s*STAGE;
        uint32_t Bs = As + ABYTES;
        #pragma unroll
        for (int i = 0; i < 2*MT; i++) {
            int idx = tid + i*256;
            int r = idx >> 3, q = idx & 7;
            int kg = k0 + q*8;
            int sz = (kg < K) ? 16 : 0;
            cpasync16s(As + (r*ASTR + q*8)*2,
                       X + (rowbase + r)*(size_t)K + min(kg, K-8), sz);
        }
        #pragma unroll
        for (int i = 0; i < 4; i++) {
            int idx = tid + i*256;
            int kr = idx >> 4, qn = idx & 15;
            int kg = k0 + kr;
            int ng = by*128 + qn*8;
            int sz = (kg < K && ng < Mout) ? 16 : 0;
            cpasync16s(Bs + (kr*BSTR + qn*8)*2,
                       W16 + (size_t)min(kg, K-1)*Mout + min(ng, Mout-8), sz);
        }
        CP_COMMIT();
    };

    issue(0);
    if (NC > 1) issue(1);

    for (int c = 0; c < NC; c++) {
        if (c + 2 < NC) issue(c + 2);
        int pending = min(2, NC - c - 1);
        if (pending >= 2)      asm volatile("cp.async.wait_group 2;");
        else if (pending == 1) asm volatile("cp.async.wait_group 1;");
        else                   asm volatile("cp.async.wait_group 0;");
        __syncthreads();
        uint32_t As = sbase + (c % NSTG)*STAGE;
        uint32_t Bs = As + ABYTES;
        #pragma unroll
        for (int kk = 0; kk < 64; kk += 16) {
            uint32_t a[MT][4];
            #pragma unroll
            for (int mt = 0; mt < MT; mt++) {
                uint32_t ad = As + (((warp_m*MT*16 + mt*16 + li)*ASTR) + kk + h8)*2;
                LDSM4(a[mt][0], a[mt][1], a[mt][2], a[mt][3], ad);
            }
            uint32_t b[4][4];
            #pragma unroll
            for (int nt2 = 0; nt2 < 4; nt2++) {
                uint32_t bd = Bs + ((kk + li)*BSTR + warp_n*64 + nt2*16 + h8)*2;
                LDSM4T(b[nt2][0], b[nt2][1], b[nt2][2], b[nt2][3], bd);
            }
            #pragma unroll
            for (int mt = 0; mt < MT; mt++)
                #pragma unroll
                for (int nt = 0; nt < 8; nt++)
                    mma16(acc[mt][nt], a[mt], b[nt>>1][(nt&1)*2], b[nt>>1][(nt&1)*2+1]);
        }
        __syncthreads();
    }

    // epilogue: bias/BN/ReLU -> fp16
    const int g = lane >> 2, tp = (lane & 3) * 2;
    #pragma unroll
    for (int nt = 0; nt < 8; nt++) {
        int base = by*128 + warp_n*64 + nt*8;
        if (base >= Mout) break;
        int m = base + tp;
        float bi0 = __ldg(&bias[m]), bi1 = __ldg(&bias[m+1]);
        float s0 = 0.f, s1 = 0.f, t0 = 0.f, t1 = 0.f;
        if (bnrelu) {
            s0 = __ldg(&bns[m]); s1 = __ldg(&bns[m+1]);
            t0 = __ldg(&bnt[m]); t1 = __ldg(&bnt[m+1]);
        }
        #pragma unroll
        for (int mt = 0; mt < MT; mt++) {
            #pragma unroll
            for (int h = 0; h < 2; h++) {
                int pt = (int)rowbase + warp_m*MT*16 + mt*16 + h*8 + g;
                float x0 = acc[mt][nt][2*h]   + bi0;
                float x1 = acc[mt][nt][2*h+1] + bi1;
                if (bnrelu) {
                    x0 = fmaxf(fmaf(x0, s0, t0), 0.f);
                    x1 = fmaxf(fmaf(x1, s1, t1), 0.f);
                }
                *(__half2*)&Y[(size_t)pt*Cout + coloff + m] = __floats2half2_rn(x0, x1);
            }
        }
    }
}

// ---------------- fused heads: score + L2-normalized vf ----------------
__global__ void k_heads(const float* __restrict__ w, const float* __restrict__ b,
                        const unsigned short* __restrict__ S,
                        const unsigned short* __restrict__ FP,
                        float* __restrict__ outScore, float* __restrict__ outVf) {
    int t = blockIdx.x*blockDim.x + threadIdx.x;
    int n = t >> 5, lane = t & 31;
    if (n >= NP) return;
    uint2 su = *(const uint2*)&S[(size_t)n*128 + lane*4];
    __half2 s0 = *(__half2*)&su.x, s1 = *(__half2*)&su.y;
    float4 wv = *(const float4*)&w[lane*4];
    float sacc = __low2float(s0)*wv.x + __high2float(s0)*wv.y
               + __low2float(s1)*wv.z + __high2float(s1)*wv.w;
    uint2 fu = *(const uint2*)&FP[(size_t)n*128 + lane*4];
    __half2 f0 = *(__half2*)&fu.x, f1 = *(__half2*)&fu.y;
    float v0 = __low2float(f0), v1 = __high2float(f0);
    float v2 = __low2float(f1), v3 = __high2float(f1);
    float ss = v0*v0 + v1*v1 + v2*v2 + v3*v3;
    #pragma unroll
    for (int o = 16; o > 0; o >>= 1) {
        sacc += __shfl_xor_sync(0xffffffff, sacc, o);
        ss   += __shfl_xor_sync(0xffffffff, ss, o);
    }
    if (lane == 0) outScore[n] = 1.f / (1.f + expf(-(sacc + b[0])));
    float inv = 1.f / fmaxf(sqrtf(ss), 1e-12f);
    *(float4*)&outVf[(size_t)n*128 + lane*4] =
        make_float4(v0*inv, v1*inv, v2*inv, v3*inv);
}

extern "C" void kernel_launch(void* const* d_in, const int* in_sizes, int n_in,
                              void* d_out, int out_size) {
    const float* pcd_xyz = (const float*)d_in[0];
    const float* rgb_xyz = (const float*)d_in[1];
    const float* pcd_f   = (const float*)d_in[2];
    const float* rgb_f   = (const float*)d_in[3];
    const float* cc1_w = (const float*)d_in[4];  const float* cc1_b = (const float*)d_in[5];
    const float* cc_bn = (const float*)d_in[6];
    const float* cc2_w = (const float*)d_in[7];  const float* cc2_b = (const float*)d_in[8];
    const float* co1_w = (const float*)d_in[9];  const float* co1_b = (const float*)d_in[10];
    const float* co_bn = (const float*)d_in[11];
    const float* co2_w = (const float*)d_in[12]; const float* co2_b = (const float*)d_in[13];
    const float* dh1_w = (const float*)d_in[14]; const float* dh1_b = (const float*)d_in[15];
    const float* dh1_bn= (const float*)d_in[16];
    const float* dh2_w = (const float*)d_in[17]; const float* dh2_b = (const float*)d_in[18];
    const float* dh2_bn= (const float*)d_in[19];
    const float* dh3_w = (const float*)d_in[20]; const float* dh3_b = (const float*)d_in[21];
    const float* sh1_w = (const float*)d_in[22]; const float* sh1_b = (const float*)d_in[23];
    const float* sh_bn = (const float*)d_in[24];
    const float* sh2_w = (const float*)d_in[25]; const float* sh2_b = (const float*)d_in[26];
    float* out = (float*)d_out;

    unsigned short *hw, *rgbt, *hA, *hB, *hC;
    float *bns, *bnt;
    cudaGetSymbolAddress((void**)&hw, d_hw);
    cudaGetSymbolAddress((void**)&rgbt, d_rgbt);
    cudaGetSymbolAddress((void**)&hA, d_hA);
    cudaGetSymbolAddress((void**)&hB, d_hB);
    cudaGetSymbolAddress((void**)&hC, d_hC);
    cudaGetSymbolAddress((void**)&bns, d_bns);
    cudaGetSymbolAddress((void**)&bnt, d_bnt);

    const int STAGE1 = 64*ASTR*2 + 64*BSTR*2;    // 26624
    const int STAGE2 = 128*ASTR*2 + 64*BSTR*2;   // 35840
    cudaFuncSetAttribute(k_mma<1>, cudaFuncAttributeMaxDynamicSharedMemorySize, NSTG*STAGE1);
    cudaFuncSetAttribute(k_mma<2>, cudaFuncAttributeMaxDynamicSharedMemorySize, NSTG*STAGE2);

    WSegs ws;
    const float* srcs[8] = {cc1_w, cc2_w, co1_w, co2_w, dh1_w, dh2_w, dh3_w, sh1_w};
    int Ms[8]   = {384, 128, 256, 128, 160, 160, 128, 128};
    int Ks[8]   = {384, 384, 256, 256, 160, 160, 160, 128};
    int offs[8] = {0, 147456, 196608, 262144, 294912, 320512, 346112, 366592};
    for (int i = 0; i < 8; i++) { ws.s[i] = srcs[i]; ws.M[i] = Ms[i]; ws.K[i] = Ks[i]; ws.off[i] = offs[i]; }
    BNSrc bnsrc;
    bnsrc.p[0] = cc_bn; bnsrc.p[1] = co_bn; bnsrc.p[2] = dh1_bn;
    bnsrc.p[3] = dh2_bn; bnsrc.p[4] = sh_bn;

    // ---- prep ----
    k_prep<<<(PREP_TOT+255)/256, 256>>>(ws, bnsrc);
    k_build<<<(NR+255)/256, 256>>>(rgb_xyz);
    k_3nn<<<(NP+127)/128, 128>>>(pcd_xyz);
    k_trans16<<<dim3(NR/32, 4), dim3(32,8)>>>(rgb_f, rgbt, 128, NR, 128, 0);
    k_gather16<<<(NP*32)/256, 256>>>(rgbt);
    cudaMemcpyAsync(out, pcd_xyz, (size_t)NP*3*sizeof(float), cudaMemcpyDeviceToDevice);

    // ---- fp16 mma GEMM chain (mixed tiling) ----
    const __half *XA = (const __half*)hA, *XB = (const __half*)hB, *XC = (const __half*)hC;
    __half *YA = (__half*)hA, *YB = (__half*)hB, *YC = (__half*)hC;
    const __half* W = (const __half*)hw;
    // cc1: hA[384] -> hB[384], BN+ReLU  (BM=128: 128x3)
    k_mma<2><<<dim3(128,3), 256, NSTG*STAGE2>>>(XA, W+offs[0], YB, cc1_b, bns,       bnt,       384, 384, 384, 0, 1);
    // cc2: hB[384] -> hC cols 0..127 (stride 256)  (BM=64: 256 CTAs)
    k_mma<1><<<dim3(256,1), 256, NSTG*STAGE1>>>(XB, W+offs[1], YC, cc2_b, nullptr,   nullptr,   384, 128, 256, 0, 0);
    // co1: hC[256] -> hA[256], BN+ReLU  (BM=128: 128x2)
    k_mma<2><<<dim3(128,2), 256, NSTG*STAGE2>>>(XC, W+offs[2], YA, co1_b, bns+384,   bnt+384,   256, 256, 256, 0, 1);
    // pcd_features -> hB cols 0..31 (stride 160)
    k_trans16<<<dim3(NP/32, 1), dim3(32,8)>>>(pcd_f, hB, 32, NP, 160, 0);
    // co2: hA[256] -> hB cols 32..159  (BM=64)
    k_mma<1><<<dim3(256,1), 256, NSTG*STAGE1>>>(XA, W+offs[3], YB, co2_b, nullptr,   nullptr,   256, 128, 160, 32, 0);
    // dh1: hB[160] -> hC[160], BN+ReLU  (BM=128)
    k_mma<2><<<dim3(128,2), 256, NSTG*STAGE2>>>(XB, W+offs[4], YC, dh1_b, bns+2*384, bnt+2*384, 160, 160, 160, 0, 1);
    // dh2: hC[160] -> hA[160], BN+ReLU  (BM=128)
    k_mma<2><<<dim3(128,2), 256, NSTG*STAGE2>>>(XC, W+offs[5], YA, dh2_b, bns+3*384, bnt+3*384, 160, 160, 160, 0, 1);
    // dh3: hA[160] -> hB[128]  (fp)  (BM=64)
    k_mma<1><<<dim3(256,1), 256, NSTG*STAGE1>>>(XA, W+offs[6], YB, dh3_b, nullptr,   nullptr,   160, 128, 128, 0, 0);
    // sh1: hB[128] -> hC[128], BN+ReLU  (BM=64)
    k_mma<1><<<dim3(256,1), 256, NSTG*STAGE1>>>(XB, W+offs[7], YC, sh1_b, bns+4*384, bnt+4*384, 128, 128, 128, 0, 1);

    // ---- outputs: [pcd_xyz NP*3][scores NP][vf NP*128] ----
    k_heads<<<(NP*32)/256, 256>>>(sh2_w, sh2_b, hC, hB,
                                  out + (size_t)NP*3, out + (size_t)NP*4);
}